// round 16
// baseline (speedup 1.0000x reference)
#include <cuda_runtime.h>

// SimpleTTS decoder-only. Recurrence folded to h-only:
//   g_t = Wcomb @ h_{t-1} + bcomb,  Wcomb = dec_Whh + dec_Wih @ lin_W
// Persistent 128-CTA kernel, weights register-resident (128 regs/thread).
// Handshake (R11/R13/R15-proven): h words ARE the sync variables (sentinel
// 2.0f, unreachable since |h| < 1): st.release per word / ld.acquire spin.
// 4 replicas, one-instruction 32-lane publish (R15).
// R16: PIPELINED poll -- 4 acquire loads in flight to the chunk, staggered
// ~96ns. Sampling period drops ~730cy -> ~190cy, killing the miss-retry
// quantization (first poll always misses; single-poll detect cost ~2x RT).

#define HID   1024
#define GATES 4096
#define MEL   80
#define NCTA  128
#define JPC   8
#define NTHR  256          // 8 warps
#define GRID  148
#define MAXT  1024
#define TT    8
#define NREP  4
#define SENT  0x40000000u  // 2.0f

__device__ float d_Wcomb[GATES * HID];          // 16.7 MB
__device__ float d_bcomb[GATES];
__device__ float d_b0[GATES];
__device__ float d_hrep[NREP][MAXT * HID];      // 16 MB, sentinel-poisoned

__device__ __forceinline__ float fast_sig(float x) {
    return __fdividef(1.0f, 1.0f + __expf(-x));
}
__device__ __forceinline__ float fast_tanh(float x) {
    x = fminf(fmaxf(x, -15.0f), 15.0f);
    float e = __expf(-2.0f * x);
    return __fdividef(1.0f - e, 1.0f + e);
}
__device__ __forceinline__ void fma2(unsigned long long& acc,
                                     unsigned long long a, unsigned long long b) {
    asm("fma.rn.f32x2 %0, %1, %2, %0;" : "+l"(acc) : "l"(a), "l"(b));
}
__device__ __forceinline__ float2 unpack2(unsigned long long v) {
    float2 r;
    asm("mov.b64 {%0,%1}, %2;" : "=f"(r.x), "=f"(r.y) : "l"(v));
    return r;
}
__device__ __forceinline__ uint4 ld_acq_v4(const uint4* p) {
    uint4 v;
    asm volatile("ld.acquire.gpu.global.v4.u32 {%0,%1,%2,%3}, [%4];"
                 : "=r"(v.x), "=r"(v.y), "=r"(v.z), "=r"(v.w)
                 : "l"(p) : "memory");
    return v;
}
__device__ __forceinline__ bool v4_ok(const uint4& v) {
    return v.x != SENT && v.y != SENT && v.z != SENT && v.w != SENT;
}
// Pipelined acquire-poll: 4 loads in flight, staggered by sleeps. The check
// of slot i stalls only on slot i's return; the other three remain in
// flight, so the chunk is sampled every ~190cy instead of every ~RT+sleep.
// Every returned value is itself an acquire load (primitive unchanged).
__device__ __forceinline__ uint4 poll_pipe(const uint4* p) {
    uint4 v0 = ld_acq_v4(p);  __nanosleep(96);
    uint4 v1 = ld_acq_v4(p);  __nanosleep(96);
    uint4 v2 = ld_acq_v4(p);  __nanosleep(96);
    uint4 v3 = ld_acq_v4(p);
    for (;;) {
        if (v4_ok(v0)) return v0;
        __nanosleep(96); v0 = ld_acq_v4(p);
        if (v4_ok(v1)) return v1;
        __nanosleep(96); v1 = ld_acq_v4(p);
        if (v4_ok(v2)) return v2;
        __nanosleep(96); v2 = ld_acq_v4(p);
        if (v4_ok(v3)) return v3;
        __nanosleep(96); v3 = ld_acq_v4(p);
    }
}
__device__ __forceinline__ void st_release_f32(float* p, float v) {
    asm volatile("st.release.gpu.global.f32 [%0], %1;" :: "l"(p), "f"(v) : "memory");
}

// ---------------------------------------------------------------------------
// Prep: Wcomb = Whh + Wih @ lin_W, biases, FULL sentinel poison of all
// 4 replicas (65,536 threads x 16 uint4 = 1,048,576 uint4 = exact size).
// ---------------------------------------------------------------------------
__global__ void prep(const float* __restrict__ Wih,
                     const float* __restrict__ Whh,
                     const float* __restrict__ linW,
                     const float* __restrict__ bih,
                     const float* __restrict__ bhh,
                     const float* __restrict__ linb) {
    __shared__ float wih_s[16 * MEL];
    const int r0 = blockIdx.x * 16;
    for (int i = threadIdx.x; i < 16 * MEL; i += 256)
        wih_s[i] = Wih[r0 * MEL + i];
    __syncthreads();

    for (int c = threadIdx.x; c < HID; c += 256) {
        float acc[16];
        #pragma unroll
        for (int r = 0; r < 16; ++r) acc[r] = 0.0f;
        for (int k = 0; k < MEL; ++k) {
            float lw = __ldg(linW + (size_t)k * HID + c);
            #pragma unroll
            for (int r = 0; r < 16; ++r) acc[r] = fmaf(wih_s[r * MEL + k], lw, acc[r]);
        }
        #pragma unroll
        for (int r = 0; r < 16; ++r)
            d_Wcomb[(size_t)(r0 + r) * HID + c] =
                Whh[(size_t)(r0 + r) * HID + c] + acc[r];
    }

    if (threadIdx.x < 16) {
        int g = r0 + threadIdx.x;
        float s = bih[g] + bhh[g];
        d_b0[g] = s;
        float a = 0.0f;
        #pragma unroll 8
        for (int k = 0; k < MEL; ++k) a = fmaf(wih_s[threadIdx.x * MEL + k], linb[k], a);
        d_bcomb[g] = s + a;
    }

    {   // full poison of all 4 replicas, exact bounds, coalesced
        const uint4 poison = make_uint4(SENT, SENT, SENT, SENT);
        uint4* hh = (uint4*)d_hrep;
        int gid = blockIdx.x * 256 + threadIdx.x;   // 0..65535
        #pragma unroll
        for (int k = 0; k < 16; ++k) hh[(size_t)k * 65536 + gid] = poison;
    }
}

// ---------------------------------------------------------------------------
// Persistent recurrence + fused finalize. 148 CTAs launched; 128 work.
// 8 dot warps; warp w owns h cols [128w, 128w+128). Lane l owns gate-row
//   grow = (l>>3)*HID + ct*JPC + (l&7).
// Warp 0 tail: ALL 32 lanes compute c/h for element l&7 (gate values are
// broadcast to all lanes); lane l release-stores to replica l>>3 (one
// instruction, 4 replicas). Consumer CTA ct polls replica ct>>5.
// ---------------------------------------------------------------------------
__global__ void __launch_bounds__(NTHR, 1) tts_main(float* __restrict__ out,
                                                    const float* __restrict__ linW,
                                                    const float* __restrict__ linb,
                                                    int T, int B) {
    if (blockIdx.x >= NCTA) return;

    __shared__ float h_all[TT * HID];       // main loop uses first HID floats
    __shared__ float red_s[2][256];
    __shared__ float fr[TT][MEL];

    const int tid = threadIdx.x;
    const int w   = tid >> 5;
    const int l   = tid & 31;
    const int ct  = blockIdx.x;
    const int jj  = l & 7;
    const int grow = (l >> 3) * HID + ct * JPC + jj;
    float* const myrep  = d_hrep[ct >> 5];          // replica this CTA polls
    float* const pubrep = d_hrep[l >> 3];           // replica this lane writes

    // 128-float register weight slice packed as 64 f32x2.
    unsigned long long W2[64];
    {
        const longlong2* wg =
            (const longlong2*)(d_Wcomb + (size_t)grow * HID + (w << 7));
        #pragma unroll
        for (int k = 0; k < 32; ++k) {
            longlong2 v = wg[k];
            W2[2 * k]     = (unsigned long long)v.x;
            W2[2 * k + 1] = (unsigned long long)v.y;
        }
    }
    const float bc = d_bcomb[grow];
    float c = 0.0f;   // warp 0: every lane carries c for element jj (replicated)

    // ---- step 0 (h = x = 0): warp 0, all lanes compute, 4-replica store ----
    if (w == 0) {
        float gv = d_b0[grow];
        float vi = __shfl_sync(0xffffffffu, gv, jj);
        float vg = __shfl_sync(0xffffffffu, gv, jj + 16);
        float vo = __shfl_sync(0xffffffffu, gv, jj + 24);
        c = fast_sig(vi) * fast_tanh(vg);
        float hh = fast_sig(vo) * fast_tanh(c);
        st_release_f32(pubrep + ct * JPC + jj, hh);
    }

    // ---- steps 1..T-1 ----
    for (int t = 1; t < T; ++t) {
        // each lane pipeline-polls its own 16B chunk of h[t-1] (own replica)
        {
            const uint4* src =
                (const uint4*)(myrep + (size_t)(t - 1) * HID + (w << 7)) + l;
            uint4 hv = poll_pipe(src);
            ((uint4*)(h_all + (w << 7)))[l] = hv;
        }
        __syncwarp();

        // packed 128-wide dot, h broadcast from SMEM
        unsigned long long a0 = 0ull, a1 = 0ull;
        const longlong2* h2 = (const longlong2*)(h_all + (w << 7));
        #pragma unroll
        for (int k = 0; k < 32; ++k) {
            longlong2 hx = h2[k];
            fma2(a0, W2[2 * k],     (unsigned long long)hx.x);
            fma2(a1, W2[2 * k + 1], (unsigned long long)hx.y);
        }
        float2 p0 = unpack2(a0), p1 = unpack2(a1);
        red_s[t & 1][l * 8 + w] = (p0.x + p0.y) + (p1.x + p1.y);
        __syncthreads();

        if (w == 0) {
            const float4* rr = (const float4*)(&red_s[t & 1][l * 8]);
            float4 x0 = rr[0], x1 = rr[1];
            float gv = ((x0.x + x0.y) + (x0.z + x0.w)) +
                       ((x1.x + x1.y) + (x1.z + x1.w)) + bc;
            float vi = __shfl_sync(0xffffffffu, gv, jj);
            float vf = __shfl_sync(0xffffffffu, gv, jj + 8);
            float vg = __shfl_sync(0xffffffffu, gv, jj + 16);
            float vo = __shfl_sync(0xffffffffu, gv, jj + 24);
            // all 32 lanes: identical update for element jj (replicated state)
            c = fast_sig(vf) * c + fast_sig(vi) * fast_tanh(vg);
            float hh = fast_sig(vo) * fast_tanh(c);
            st_release_f32(pubrep + (size_t)t * HID + ct * JPC + jj, hh);
        }
        // red_s WAR safe: this parity is rewritten only at step t+2, after
        // the t+1 barrier, which warp 0 reaches only after this tail.
        // h_all slice WAR safe: rewritten only by the same warp's next poll.
    }

    // ===== fused finalize: CTA ct -> timesteps [ct*TT, ct*TT+TT) =====
    const int t0 = ct * TT;
    if (t0 < T) {
        for (int i = tid; i < TT * HID / 4; i += NTHR) {
            int j = i >> 8;                 // / (HID/4)
            int k = i & 255;                // uint4 index within row
            if (t0 + j < T) {
                uint4 hv = poll_pipe(
                    (const uint4*)(myrep + (size_t)(t0 + j) * HID) + k);
                ((uint4*)(h_all + j * HID))[k] = hv;
            }
        }
        __syncthreads();

        for (int m = w; m < MEL; m += 8) {
            const float* wrow = linW + (size_t)m * HID;
            float s[TT];
            #pragma unroll
            for (int j = 0; j < TT; ++j) s[j] = 0.0f;
            for (int k = l; k < HID; k += 32) {
                float wv = wrow[k];
                #pragma unroll
                for (int j = 0; j < TT; ++j) s[j] = fmaf(wv, h_all[j * HID + k], s[j]);
            }
            #pragma unroll
            for (int j = 0; j < TT; ++j) {
                #pragma unroll
                for (int off = 16; off; off >>= 1)
                    s[j] += __shfl_down_sync(0xffffffffu, s[j], off);
            }
            if (l == 0) {
                float bb = linb[m];
                #pragma unroll
                for (int j = 0; j < TT; ++j) fr[j][m] = s[j] + bb;
            }
        }
        __syncthreads();

        const int tot = B * TT * MEL;
        for (int i = tid; i < tot; i += NTHR) {
            int b = i / (TT * MEL);
            int r = i - b * (TT * MEL);
            int j = r / MEL;
            int m = r - j * MEL;
            int t = t0 + j;
            if (t < T) out[((size_t)b * T + t) * MEL + m] = fr[j][m];
        }
    }
}

// ---------------------------------------------------------------------------
extern "C" void kernel_launch(void* const* d_in, const int* in_sizes, int n_in,
                              void* d_out, int out_size) {
    if (n_in < 6) return;
    const float* dec_Wih = (const float*)d_in[n_in - 6];
    const float* dec_Whh = (const float*)d_in[n_in - 5];
    const float* dec_bih = (const float*)d_in[n_in - 4];
    const float* dec_bhh = (const float*)d_in[n_in - 3];
    const float* lin_W   = (const float*)d_in[n_in - 2];
    const float* lin_b   = (const float*)d_in[n_in - 1];

    const int B = in_sizes[1];
    int T = out_size / (B * MEL);
    if (T > MAXT) T = MAXT;
    if (T <= 0) return;

    prep    <<<GATES / 16, 256>>>(dec_Wih, dec_Whh, lin_W, dec_bih, dec_bhh, lin_b);
    tts_main<<<GRID, NTHR>>>((float*)d_out, lin_W, lin_b, T, B);
}

// round 17
// speedup vs baseline: 1.1914x; 1.1914x over previous
#include <cuda_runtime.h>

// SimpleTTS decoder-only. Recurrence folded to h-only:
//   g_t = Wcomb @ h_{t-1} + bcomb,  Wcomb = dec_Whh + dec_Wih @ lin_W
// Persistent 128-CTA kernel, weights register-resident (128 regs/thread).
// Handshake (R11/R13/R15-proven, unchanged): h words ARE the sync variables
// (sentinel 2.0f, unreachable since |h|<1); st.release publish, acquire-load
// spin w/ 64ns backoff, 4 replicas, consumer CTA ct polls replica ct>>5.
// R17: ELEMENT-PER-WARP. Warp w owns all 4 gates of h element ct*8+w:
// in-warp butterfly reduction -> every warp does its own activations and
// publish in parallel. Kills the warp-0 tail phase + red_s entirely.
// One __syncthreads per step; double-buffered SMEM staging (barrier
// interlock makes 2 buffers sufficient).

#define HID   1024
#define GATES 4096
#define MEL   80
#define NCTA  128
#define JPC   8
#define NTHR  256          // 8 warps
#define GRID  148
#define MAXT  1024
#define TT    8
#define NREP  4
#define SENT  0x40000000u  // 2.0f

__device__ float d_Wcomb[GATES * HID];          // 16.7 MB
__device__ float d_bcomb[GATES];
__device__ float d_b0[GATES];
__device__ float d_hrep[NREP][MAXT * HID];      // 16 MB, sentinel-poisoned

__device__ __forceinline__ float fast_sig(float x) {
    return __fdividef(1.0f, 1.0f + __expf(-x));
}
__device__ __forceinline__ float fast_tanh(float x) {
    x = fminf(fmaxf(x, -15.0f), 15.0f);
    float e = __expf(-2.0f * x);
    return __fdividef(1.0f - e, 1.0f + e);
}
__device__ __forceinline__ void fma2(unsigned long long& acc,
                                     unsigned long long a, unsigned long long b) {
    asm("fma.rn.f32x2 %0, %1, %2, %0;" : "+l"(acc) : "l"(a), "l"(b));
}
__device__ __forceinline__ float2 unpack2(unsigned long long v) {
    float2 r;
    asm("mov.b64 {%0,%1}, %2;" : "=f"(r.x), "=f"(r.y) : "l"(v));
    return r;
}
// Acquire-poll one 16B chunk; every word validated against the sentinel.
__device__ __forceinline__ uint4 poll_v4_acq(const uint4* p) {
    uint4 v;
    for (;;) {
        asm volatile("ld.acquire.gpu.global.v4.u32 {%0,%1,%2,%3}, [%4];"
                     : "=r"(v.x), "=r"(v.y), "=r"(v.z), "=r"(v.w)
                     : "l"(p) : "memory");
        if (v.x != SENT && v.y != SENT && v.z != SENT && v.w != SENT) return v;
        __nanosleep(64);
    }
}
__device__ __forceinline__ void st_release_f32(float* p, float v) {
    asm volatile("st.release.gpu.global.f32 [%0], %1;" :: "l"(p), "f"(v) : "memory");
}

// ---------------------------------------------------------------------------
// Prep: Wcomb = Whh + Wih @ lin_W, biases, FULL sentinel poison of all
// 4 replicas (65,536 threads x 16 uint4 = 1,048,576 uint4 = exact size).
// ---------------------------------------------------------------------------
__global__ void prep(const float* __restrict__ Wih,
                     const float* __restrict__ Whh,
                     const float* __restrict__ linW,
                     const float* __restrict__ bih,
                     const float* __restrict__ bhh,
                     const float* __restrict__ linb) {
    __shared__ float wih_s[16 * MEL];
    const int r0 = blockIdx.x * 16;
    for (int i = threadIdx.x; i < 16 * MEL; i += 256)
        wih_s[i] = Wih[r0 * MEL + i];
    __syncthreads();

    for (int c = threadIdx.x; c < HID; c += 256) {
        float acc[16];
        #pragma unroll
        for (int r = 0; r < 16; ++r) acc[r] = 0.0f;
        for (int k = 0; k < MEL; ++k) {
            float lw = __ldg(linW + (size_t)k * HID + c);
            #pragma unroll
            for (int r = 0; r < 16; ++r) acc[r] = fmaf(wih_s[r * MEL + k], lw, acc[r]);
        }
        #pragma unroll
        for (int r = 0; r < 16; ++r)
            d_Wcomb[(size_t)(r0 + r) * HID + c] =
                Whh[(size_t)(r0 + r) * HID + c] + acc[r];
    }

    if (threadIdx.x < 16) {
        int g = r0 + threadIdx.x;
        float s = bih[g] + bhh[g];
        d_b0[g] = s;
        float a = 0.0f;
        #pragma unroll 8
        for (int k = 0; k < MEL; ++k) a = fmaf(wih_s[threadIdx.x * MEL + k], linb[k], a);
        d_bcomb[g] = s + a;
    }

    {   // full poison of all 4 replicas, exact bounds, coalesced
        const uint4 poison = make_uint4(SENT, SENT, SENT, SENT);
        uint4* hh = (uint4*)d_hrep;
        int gid = blockIdx.x * 256 + threadIdx.x;   // 0..65535
        #pragma unroll
        for (int k = 0; k < 16; ++k) hh[(size_t)k * 65536 + gid] = poison;
    }
}

// ---------------------------------------------------------------------------
// Persistent recurrence + fused finalize. 148 CTAs launched; 128 work.
// Warp w owns h element e = ct*8 + w. Lane l holds rows {q*1024+e, q=0..3}
// x cols {2l+64j, 2l+64j+1 : j=0..15} (128 weights = 64 f32x2).
// Staging: thread tid polls uint4 chunk tid of h[t-1] into hbuf[t&1].
// After barrier: 4-way dot, 5-level bfly (all lanes get all 4 gate sums),
// redundant per-lane c/h update, lanes 0/8/16/24 publish to 4 replicas.
// ---------------------------------------------------------------------------
__global__ void __launch_bounds__(NTHR, 1) tts_main(float* __restrict__ out,
                                                    const float* __restrict__ linW,
                                                    const float* __restrict__ linb,
                                                    int T, int B) {
    if (blockIdx.x >= NCTA) return;

    __shared__ float h_all[TT * HID];       // finalize buffer; first 8KB =
    float (*hbuf)[HID] = (float(*)[HID])h_all;  // main-loop double buffer
    __shared__ float fr[TT][MEL];

    const int tid = threadIdx.x;
    const int w   = tid >> 5;
    const int l   = tid & 31;
    const int ct  = blockIdx.x;
    const int e   = ct * JPC + w;           // global h element of this warp
    float* const myrep = d_hrep[ct >> 5];   // replica this CTA polls

    // Weights: 4 gate rows x 16 col-pairs, packed f32x2 (128 regs).
    unsigned long long W2[4][16];
    float bc[4];
    #pragma unroll
    for (int q = 0; q < 4; ++q) {
        const size_t base = (size_t)(q * HID + e) * HID + 2 * l;
        #pragma unroll
        for (int j = 0; j < 16; ++j)
            W2[q][j] = *(const unsigned long long*)(d_Wcomb + base + 64 * j);
        bc[q] = d_bcomb[q * HID + e];
    }

    // ---- step 0 (h = x = 0): gates = b0; all lanes replicate c ----
    float c;
    {
        float gi = d_b0[e];
        float gg = d_b0[2 * HID + e];
        float go = d_b0[3 * HID + e];
        c = fast_sig(gi) * fast_tanh(gg);
        float h0 = fast_sig(go) * fast_tanh(c);
        if ((l & 7) == 0)
            st_release_f32(d_hrep[l >> 3] + e, h0);
    }

    // ---- steps 1..T-1 ----
    for (int t = 1; t < T; ++t) {
        // stage: thread tid acquire-polls its uint4 chunk of h[t-1]
        {
            const uint4* src = (const uint4*)(myrep + (size_t)(t - 1) * HID) + tid;
            uint4 hv = poll_v4_acq(src);
            ((uint4*)hbuf[t & 1])[tid] = hv;
        }
        __syncthreads();

        // 4-row dot over packed h pairs (LDS64, 2-way conflict max)
        unsigned long long a0 = 0ull, a1 = 0ull, a2 = 0ull, a3 = 0ull;
        const unsigned long long* hb = (const unsigned long long*)hbuf[t & 1];
        #pragma unroll
        for (int j = 0; j < 16; ++j) {
            unsigned long long hp = hb[l + 32 * j];
            fma2(a0, W2[0][j], hp);
            fma2(a1, W2[1][j], hp);
            fma2(a2, W2[2][j], hp);
            fma2(a3, W2[3][j], hp);
        }
        float s0, s1, s2, s3;
        {
            float2 p;
            p = unpack2(a0); s0 = p.x + p.y;
            p = unpack2(a1); s1 = p.x + p.y;
            p = unpack2(a2); s2 = p.x + p.y;
            p = unpack2(a3); s3 = p.x + p.y;
            #pragma unroll
            for (int off = 16; off; off >>= 1) {
                s0 += __shfl_xor_sync(0xffffffffu, s0, off);
                s1 += __shfl_xor_sync(0xffffffffu, s1, off);
                s2 += __shfl_xor_sync(0xffffffffu, s2, off);
                s3 += __shfl_xor_sync(0xffffffffu, s3, off);
            }
            s0 += bc[0]; s1 += bc[1]; s2 += bc[2]; s3 += bc[3];
        }
        // all lanes: identical LSTM update for element e
        c = fast_sig(s1) * c + fast_sig(s0) * fast_tanh(s2);
        float hh = fast_sig(s3) * fast_tanh(c);
        if ((l & 7) == 0)
            st_release_f32(d_hrep[l >> 3] + (size_t)t * HID + e, hh);
        // hbuf WAR safe: next write to this parity happens at step t+2,
        // after the t+1 barrier, which requires all warps past their t dot.
    }

    __syncthreads();   // protect hbuf before finalize overwrites h_all

    // ===== fused finalize: CTA ct -> timesteps [ct*TT, ct*TT+TT) =====
    const int t0 = ct * TT;
    if (t0 < T) {
        for (int i = tid; i < TT * HID / 4; i += NTHR) {
            int j = i >> 8;                 // / (HID/4)
            int k = i & 255;                // uint4 index within row
            if (t0 + j < T) {
                uint4 hv = poll_v4_acq(
                    (const uint4*)(myrep + (size_t)(t0 + j) * HID) + k);
                ((uint4*)(h_all + j * HID))[k] = hv;
            }
        }
        __syncthreads();

        for (int m = w; m < MEL; m += 8) {
            const float* wrow = linW + (size_t)m * HID;
            float s[TT];
            #pragma unroll
            for (int j = 0; j < TT; ++j) s[j] = 0.0f;
            for (int k = l; k < HID; k += 32) {
                float wv = wrow[k];
                #pragma unroll
                for (int j = 0; j < TT; ++j) s[j] = fmaf(wv, h_all[j * HID + k], s[j]);
            }
            #pragma unroll
            for (int j = 0; j < TT; ++j) {
                #pragma unroll
                for (int off = 16; off; off >>= 1)
                    s[j] += __shfl_down_sync(0xffffffffu, s[j], off);
            }
            if (l == 0) {
                float bb = linb[m];
                #pragma unroll
                for (int j = 0; j < TT; ++j) fr[j][m] = s[j] + bb;
            }
        }
        __syncthreads();

        const int tot = B * TT * MEL;
        for (int i = tid; i < tot; i += NTHR) {
            int b = i / (TT * MEL);
            int r = i - b * (TT * MEL);
            int j = r / MEL;
            int m = r - j * MEL;
            int t = t0 + j;
            if (t < T) out[((size_t)b * T + t) * MEL + m] = fr[j][m];
        }
    }
}

// ---------------------------------------------------------------------------
extern "C" void kernel_launch(void* const* d_in, const int* in_sizes, int n_in,
                              void* d_out, int out_size) {
    if (n_in < 6) return;
    const float* dec_Wih = (const float*)d_in[n_in - 6];
    const float* dec_Whh = (const float*)d_in[n_in - 5];
    const float* dec_bih = (const float*)d_in[n_in - 4];
    const float* dec_bhh = (const float*)d_in[n_in - 3];
    const float* lin_W   = (const float*)d_in[n_in - 2];
    const float* lin_b   = (const float*)d_in[n_in - 1];

    const int B = in_sizes[1];
    int T = out_size / (B * MEL);
    if (T > MAXT) T = MAXT;
    if (T <= 0) return;

    prep    <<<GATES / 16, 256>>>(dec_Wih, dec_Whh, lin_W, dec_bih, dec_bhh, lin_b);
    tts_main<<<GRID, NTHR>>>((float*)d_out, lin_W, lin_b, T, B);
}